// round 11
// baseline (speedup 1.0000x reference)
#include <cuda_runtime.h>
#include <math.h>

#define DD 6
#define SEQ 128
typedef unsigned long long u64;

__device__ __forceinline__ u64 pack2(float lo, float hi) {
    u64 r; asm("mov.b64 %0, {%1, %2};" : "=l"(r) : "f"(lo), "f"(hi)); return r;
}
__device__ __forceinline__ void unpack2(u64 v, float& lo, float& hi) {
    asm("mov.b64 {%0, %1}, %2;" : "=f"(lo), "=f"(hi) : "l"(v));
}
__device__ __forceinline__ u64 ffma2(u64 a, u64 b, u64 c) {
    u64 d; asm("fma.rn.f32x2 %0, %1, %2, %3;" : "=l"(d) : "l"(a), "l"(b), "l"(c)); return d;
}
__device__ __forceinline__ u64 fmul2(u64 a, u64 b) {
    u64 d; asm("mul.rn.f32x2 %0, %1, %2;" : "=l"(d) : "l"(a), "l"(b)); return d;
}
__device__ __forceinline__ u64 fadd2(u64 a, u64 b) {
    u64 d; asm("add.rn.f32x2 %0, %1, %2;" : "=l"(d) : "l"(a), "l"(b)); return d;
}
__device__ __forceinline__ float ex2f(float x) {
    float y; asm("ex2.approx.f32 %0, %1;" : "=f"(y) : "f"(x)); return y;
}
__device__ __forceinline__ float rcpf(float x) {
    float y; asm("rcp.approx.f32 %0, %1;" : "=f"(y) : "f"(x)); return y;
}

// weight-dup smem offsets (u64 units): each entry = (w,w)
#define WQ   0      // 108
#define BQ   108    // 18
#define WO   126    // 36
#define BO   162    // 6
#define W1   168    // 36
#define B1   204    // 6
#define W2   210    // 36
#define B2   246    // 6
#define L1W  252    // 6
#define L1B  258    // 6
#define L2W  264    // 6
#define L2B  270    // 6

// out-proj + residual + LN2 + FFN + residual, packed over 2 batches.
// __noinline__: confines epilogue register appetite to a call frame.
__device__ __noinline__ void epilogue2(
    const u64* __restrict__ o2,
    const float* __restrict__ x0, const float* __restrict__ x1,
    float* __restrict__ out0, float* __restrict__ out1,
    const u64* __restrict__ W)
{
    // reload x packed (L2 hit)
    u64 xp[DD];
#pragma unroll
    for (int k = 0; k < 3; ++k) {
        float2 a = ((const float2*)x0)[k];
        float2 b = ((const float2*)x1)[k];
        xp[2 * k]     = pack2(a.x, b.x);
        xp[2 * k + 1] = pack2(a.y, b.y);
    }
    // out-proj + residual
    u64 y2[DD];
#pragma unroll
    for (int d = 0; d < DD; ++d) {
        u64 a = W[BO + d];
#pragma unroll
        for (int i = 0; i < DD; ++i) a = ffma2(o2[i], W[WO + i * 6 + d], a);
        y2[d] = fadd2(xp[d], a);
    }
    // LN2 packed
    const u64 sixth2 = pack2(1.f / DD, 1.f / DD);
    const u64 neg2   = pack2(-1.f, -1.f);
    u64 sum2 = y2[0];
#pragma unroll
    for (int d = 1; d < DD; ++d) sum2 = fadd2(sum2, y2[d]);
    u64 nm2 = fmul2(fmul2(sum2, sixth2), neg2);
    u64 var2 = 0ull;
    u64 d2[DD];
#pragma unroll
    for (int d = 0; d < DD; ++d) {
        d2[d] = fadd2(y2[d], nm2);
        var2 = ffma2(d2[d], d2[d], var2);
    }
    float vA, vB;
    unpack2(fmul2(var2, sixth2), vA, vB);
    u64 rstd2 = pack2(rsqrtf(vA + 1e-5f), rsqrtf(vB + 1e-5f));
    u64 h2[DD];
#pragma unroll
    for (int d = 0; d < DD; ++d)
        h2[d] = ffma2(fmul2(d2[d], rstd2), W[L2W + d], W[L2B + d]);
    // FFN
    u64 g2[DD];
#pragma unroll
    for (int d = 0; d < DD; ++d) {
        u64 a = W[B1 + d];
#pragma unroll
        for (int i = 0; i < DD; ++i) a = ffma2(h2[i], W[W1 + i * 6 + d], a);
        float aA, aB;
        unpack2(a, aA, aB);
        g2[d] = pack2(aA * normcdff(aA), aB * normcdff(aB));   // exact gelu
    }
    float r0[DD], r1[DD];
#pragma unroll
    for (int d = 0; d < DD; ++d) {
        u64 a = W[B2 + d];
#pragma unroll
        for (int i = 0; i < DD; ++i) a = ffma2(g2[i], W[W2 + i * 6 + d], a);
        u64 f = fadd2(y2[d], a);
        unpack2(f, r0[d], r1[d]);
    }
#pragma unroll
    for (int k = 0; k < 3; ++k) {
        ((float2*)out0)[k] = make_float2(r0[2 * k], r0[2 * k + 1]);
        ((float2*)out1)[k] = make_float2(r1[2 * k], r1[2 * k + 1]);
    }
}

__global__ __launch_bounds__(128, 4) void block_ffn_kernel(
    const float* __restrict__ x,
    const float* __restrict__ ln1_w, const float* __restrict__ ln1_b,
    const float* __restrict__ wqkv,  const float* __restrict__ bqkv,
    const float* __restrict__ wo,    const float* __restrict__ bo,
    const float* __restrict__ ln2_w, const float* __restrict__ ln2_b,
    const float* __restrict__ w1,    const float* __restrict__ b1,
    const float* __restrict__ w2,    const float* __restrict__ b2,
    float* __restrict__ out)
{
    // 2 batch-pairs per block; per pair: 128 tokens x 12 u64 (k0..5,v0..5),
    // each u64 = (batch0, batch1) packed
    __shared__ __align__(16) u64 s_kv[2 * SEQ * 12];   // 24 KB
    __shared__ u64 s_wd[276];                          // duplicated weights

    const int t    = threadIdx.x;
    const int pair = t >> 6;          // which batch-pair in block
    const int u    = t & 63;          // my query-pair: tokens 2u, 2u+1
    const int b0   = blockIdx.x * 4 + pair * 2;

    // ---- stage duplicated weights ----
    for (int idx = t; idx < 276; idx += 128) {
        float w;
        if      (idx < 108) w = wqkv[idx];
        else if (idx < 126) w = bqkv[idx - 108];
        else if (idx < 162) w = wo[idx - 126];
        else if (idx < 168) w = bo[idx - 162];
        else if (idx < 204) w = w1[idx - 168];
        else if (idx < 210) w = b1[idx - 204];
        else if (idx < 246) w = w2[idx - 210];
        else if (idx < 252) w = b2[idx - 246];
        else if (idx < 258) w = ln1_w[idx - 252];
        else if (idx < 264) w = ln1_b[idx - 258];
        else if (idx < 270) w = ln2_w[idx - 264];
        else                w = ln2_b[idx - 270];
        s_wd[idx] = pack2(w, w);
    }

    const float* xa0 = x + ((long)b0 * SEQ + 2 * u) * DD;   // token 2u, batch b0
    const float* xa1 = xa0 + SEQ * DD;                      // token 2u, batch b0+1

    // ---- load x for both tokens, packed over batches ----
    u64 xpA[DD], xpB[DD];
#pragma unroll
    for (int k = 0; k < 3; ++k) {
        float2 a0 = ((const float2*)xa0)[k];
        float2 a1 = ((const float2*)xa1)[k];
        xpA[2 * k]     = pack2(a0.x, a1.x);
        xpA[2 * k + 1] = pack2(a0.y, a1.y);
        float2 b0v = ((const float2*)(xa0 + DD))[k];
        float2 b1v = ((const float2*)(xa1 + DD))[k];
        xpB[2 * k]     = pack2(b0v.x, b1v.x);
        xpB[2 * k + 1] = pack2(b0v.y, b1v.y);
    }

    // ---- LN1 stats for both tokens (no smem needed yet) ----
    const u64 sixth2 = pack2(1.f / DD, 1.f / DD);
    const u64 neg2   = pack2(-1.f, -1.f);
    u64 sumA = xpA[0], sumB = xpB[0];
#pragma unroll
    for (int d = 1; d < DD; ++d) { sumA = fadd2(sumA, xpA[d]); sumB = fadd2(sumB, xpB[d]); }
    u64 nmA = fmul2(fmul2(sumA, sixth2), neg2);
    u64 nmB = fmul2(fmul2(sumB, sixth2), neg2);
    u64 varA = 0ull, varB = 0ull;
    u64 dmuA[DD], dmuB[DD];
#pragma unroll
    for (int d = 0; d < DD; ++d) {
        dmuA[d] = fadd2(xpA[d], nmA); varA = ffma2(dmuA[d], dmuA[d], varA);
        dmuB[d] = fadd2(xpB[d], nmB); varB = ffma2(dmuB[d], dmuB[d], varB);
    }
    float vA0, vA1, vB0, vB1;
    unpack2(fmul2(varA, sixth2), vA0, vA1);
    unpack2(fmul2(varB, sixth2), vB0, vB1);
    u64 rstdA = pack2(rsqrtf(vA0 + 1e-5f), rsqrtf(vA1 + 1e-5f));
    u64 rstdB = pack2(rsqrtf(vB0 + 1e-5f), rsqrtf(vB1 + 1e-5f));

    __syncthreads();   // weights staged

    // ---- QKV for token A then token B; fold (1/sqrt6)*log2e into q ----
    const float SCL = 0.58897937652f;
    const u64 scl2 = pack2(SCL, SCL);
    u64 qA2[DD], qB2[DD];
    {
        u64 h2[DD];
#pragma unroll
        for (int d = 0; d < DD; ++d)
            h2[d] = ffma2(fmul2(dmuA[d], rstdA), s_wd[L1W + d], s_wd[L1B + d]);
#pragma unroll
        for (int j = 0; j < DD; ++j) {
            u64 a = s_wd[BQ + j];
#pragma unroll
            for (int d = 0; d < DD; ++d) a = ffma2(h2[d], s_wd[WQ + d * 18 + j], a);
            qA2[j] = fmul2(a, scl2);
        }
        u64* row = s_kv + (pair * SEQ + 2 * u) * 12;
#pragma unroll
        for (int j = 0; j < 12; ++j) {
            u64 a = s_wd[BQ + 6 + j];
#pragma unroll
            for (int d = 0; d < DD; ++d) a = ffma2(h2[d], s_wd[WQ + d * 18 + 6 + j], a);
            row[j] = a;
        }
    }
    {
        u64 h2[DD];
#pragma unroll
        for (int d = 0; d < DD; ++d)
            h2[d] = ffma2(fmul2(dmuB[d], rstdB), s_wd[L1W + d], s_wd[L1B + d]);
#pragma unroll
        for (int j = 0; j < DD; ++j) {
            u64 a = s_wd[BQ + j];
#pragma unroll
            for (int d = 0; d < DD; ++d) a = ffma2(h2[d], s_wd[WQ + d * 18 + j], a);
            qB2[j] = fmul2(a, scl2);
        }
        u64* row = s_kv + (pair * SEQ + 2 * u + 1) * 12;
#pragma unroll
        for (int j = 0; j < 12; ++j) {
            u64 a = s_wd[BQ + 6 + j];
#pragma unroll
            for (int d = 0; d < DD; ++d) a = ffma2(h2[d], s_wd[WQ + d * 18 + 6 + j], a);
            row[j] = a;
        }
    }

    __syncthreads();   // all K/V visible

    // ---- causal attention: 1 key feeds both queries; lanes = 2 batches ----
    const u64* kvb = s_kv + pair * SEQ * 12;
    u64 aA0 = 0, aA1 = 0, aA2 = 0, aA3 = 0, aA4 = 0, aA5 = 0;
    u64 aB0 = 0, aB1 = 0, aB2 = 0, aB3 = 0, aB4 = 0, aB5 = 0;
    u64 lA2 = 0, lB2 = 0;
    const int jend = 2 * u;   // main loop: keys 0..2u valid for BOTH queries

#pragma unroll 2
    for (int j = 0; j <= jend; ++j) {
        const ulonglong2* p = (const ulonglong2*)(kvb + j * 12);
        ulonglong2 K01 = p[0], K23 = p[1], K45 = p[2];
        ulonglong2 V01 = p[3], V23 = p[4], V45 = p[5];
        u64 sa = ffma2(qA2[5], K45.y, ffma2(qA2[4], K45.x,
                 ffma2(qA2[3], K23.y, ffma2(qA2[2], K23.x,
                 ffma2(qA2[1], K01.y, fmul2(qA2[0], K01.x))))));
        u64 sb = ffma2(qB2[5], K45.y, ffma2(qB2[4], K45.x,
                 ffma2(qB2[3], K23.y, ffma2(qB2[2], K23.x,
                 ffma2(qB2[1], K01.y, fmul2(qB2[0], K01.x))))));
        float s0, s1, s2, s3;
        unpack2(sa, s0, s1); unpack2(sb, s2, s3);
        u64 pa = pack2(ex2f(s0), ex2f(s1));
        u64 pb = pack2(ex2f(s2), ex2f(s3));
        lA2 = fadd2(lA2, pa); lB2 = fadd2(lB2, pb);
        aA0 = ffma2(pa, V01.x, aA0); aB0 = ffma2(pb, V01.x, aB0);
        aA1 = ffma2(pa, V01.y, aA1); aB1 = ffma2(pb, V01.y, aB1);
        aA2 = ffma2(pa, V23.x, aA2); aB2 = ffma2(pb, V23.x, aB2);
        aA3 = ffma2(pa, V23.y, aA3); aB3 = ffma2(pb, V23.y, aB3);
        aA4 = ffma2(pa, V45.x, aA4); aB4 = ffma2(pb, V45.x, aB4);
        aA5 = ffma2(pa, V45.y, aA5); aB5 = ffma2(pb, V45.y, aB5);
    }
    // peeled diagonal: key 2u+1 attends only query B
    {
        const ulonglong2* p = (const ulonglong2*)(kvb + (2 * u + 1) * 12);
        ulonglong2 K01 = p[0], K23 = p[1], K45 = p[2];
        ulonglong2 V01 = p[3], V23 = p[4], V45 = p[5];
        u64 sb = ffma2(qB2[5], K45.y, ffma2(qB2[4], K45.x,
                 ffma2(qB2[3], K23.y, ffma2(qB2[2], K23.x,
                 ffma2(qB2[1], K01.y, fmul2(qB2[0], K01.x))))));
        float s2, s3;
        unpack2(sb, s2, s3);
        u64 pb = pack2(ex2f(s2), ex2f(s3));
        lB2 = fadd2(lB2, pb);
        aB0 = ffma2(pb, V01.x, aB0);
        aB1 = ffma2(pb, V01.y, aB1);
        aB2 = ffma2(pb, V23.x, aB2);
        aB3 = ffma2(pb, V23.y, aB3);
        aB4 = ffma2(pb, V45.x, aB4);
        aB5 = ffma2(pb, V45.y, aB5);
    }

    float l0, l1;
    unpack2(lA2, l0, l1);
    u64 invA = pack2(rcpf(l0), rcpf(l1));
    unpack2(lB2, l0, l1);
    u64 invB = pack2(rcpf(l0), rcpf(l1));
    u64 o2A[DD], o2B[DD];
    o2A[0] = fmul2(aA0, invA); o2B[0] = fmul2(aB0, invB);
    o2A[1] = fmul2(aA1, invA); o2B[1] = fmul2(aB1, invB);
    o2A[2] = fmul2(aA2, invA); o2B[2] = fmul2(aB2, invB);
    o2A[3] = fmul2(aA3, invA); o2B[3] = fmul2(aB3, invB);
    o2A[4] = fmul2(aA4, invA); o2B[4] = fmul2(aB4, invB);
    o2A[5] = fmul2(aA5, invA); o2B[5] = fmul2(aB5, invB);

    float* oa0 = out + ((long)b0 * SEQ + 2 * u) * DD;
    epilogue2(o2A, xa0,      xa1,      oa0,      oa0 + SEQ * DD,      s_wd);
    epilogue2(o2B, xa0 + DD, xa1 + DD, oa0 + DD, oa0 + SEQ * DD + DD, s_wd);
}

extern "C" void kernel_launch(void* const* d_in, const int* in_sizes, int n_in,
                              void* d_out, int out_size) {
    const float* x     = (const float*)d_in[0];
    const float* ln1_w = (const float*)d_in[1];
    const float* ln1_b = (const float*)d_in[2];
    const float* wqkv  = (const float*)d_in[3];
    const float* bqkv  = (const float*)d_in[4];
    const float* wo    = (const float*)d_in[5];
    const float* bo    = (const float*)d_in[6];
    const float* ln2_w = (const float*)d_in[7];
    const float* ln2_b = (const float*)d_in[8];
    const float* w1    = (const float*)d_in[9];
    const float* b1    = (const float*)d_in[10];
    const float* w2    = (const float*)d_in[11];
    const float* b2    = (const float*)d_in[12];
    float* out = (float*)d_out;

    const int B = in_sizes[0] / (SEQ * DD);   // 8192
    block_ffn_kernel<<<B / 4, 128>>>(x, ln1_w, ln1_b, wqkv, bqkv, wo, bo,
                                     ln2_w, ln2_b, w1, b1, w2, b2, out);
}

// round 14
// speedup vs baseline: 1.1560x; 1.1560x over previous
#include <cuda_runtime.h>
#include <math.h>

#define DD 6
#define SEQ 128
typedef unsigned long long u64;

// per-batch K/V region: 64 key-pairs * 24 floats = 1536, +4 pad so the 4
// batch bases land in distinct 16B bank-quads
#define KV_STRIDE 1540

__device__ __forceinline__ u64 pack2(float lo, float hi) {
    u64 r; asm("mov.b64 %0, {%1, %2};" : "=l"(r) : "f"(lo), "f"(hi)); return r;
}
__device__ __forceinline__ void unpack2(u64 v, float& lo, float& hi) {
    asm("mov.b64 {%0, %1}, %2;" : "=f"(lo), "=f"(hi) : "l"(v));
}
__device__ __forceinline__ u64 ffma2(u64 a, u64 b, u64 c) {
    u64 d; asm("fma.rn.f32x2 %0, %1, %2, %3;" : "=l"(d) : "l"(a), "l"(b), "l"(c)); return d;
}
__device__ __forceinline__ u64 fmul2(u64 a, u64 b) {
    u64 d; asm("mul.rn.f32x2 %0, %1, %2;" : "=l"(d) : "l"(a), "l"(b)); return d;
}
__device__ __forceinline__ u64 fadd2(u64 a, u64 b) {
    u64 d; asm("add.rn.f32x2 %0, %1, %2;" : "=l"(d) : "l"(a), "l"(b)); return d;
}
__device__ __forceinline__ float ex2f(float x) {
    float y; asm("ex2.approx.f32 %0, %1;" : "=f"(y) : "f"(x)); return y;
}
__device__ __forceinline__ float rcpf(float x) {
    float y; asm("rcp.approx.f32 %0, %1;" : "=f"(y) : "f"(x)); return y;
}

__device__ __forceinline__ u64 dot6(const u64* q, ulonglong2 K0, ulonglong2 K1, ulonglong2 K2) {
    return ffma2(q[0], K0.x,
           ffma2(q[1], K0.y,
           ffma2(q[2], K1.x,
           ffma2(q[3], K1.y,
           ffma2(q[4], K2.x,
           fmul2(q[5], K2.y))))));
}

// causal attention for query-pair uu (tokens 2uu, 2uu+1); keys-in-lanes.
__device__ __forceinline__ void attend(
    int uu, const u64* __restrict__ qa2, const u64* __restrict__ qb2,
    const float* __restrict__ kv_base, float* __restrict__ oA, float* __restrict__ oB)
{
    const ulonglong2* kvb = (const ulonglong2*)kv_base;
    u64 acca[DD], accb[DD];
#pragma unroll
    for (int d = 0; d < DD; ++d) { acca[d] = 0ull; accb[d] = 0ull; }
    u64 la2 = 0ull, lb2 = 0ull;

#pragma unroll 2
    for (int j = 0; j < uu; ++j) {
        const ulonglong2* p = kvb + j * 6;
        ulonglong2 K0 = p[0], K1 = p[1], K2 = p[2];
        ulonglong2 V0 = p[3], V1 = p[4], V2 = p[5];
        u64 sa = dot6(qa2, K0, K1, K2);
        u64 sb = dot6(qb2, K0, K1, K2);
        float saA, saB, sbA, sbB;
        unpack2(sa, saA, saB); unpack2(sb, sbA, sbB);
        u64 pa = pack2(ex2f(saA), ex2f(saB));
        u64 pb = pack2(ex2f(sbA), ex2f(sbB));
        la2 = fadd2(la2, pa); lb2 = fadd2(lb2, pb);
        acca[0] = ffma2(pa, V0.x, acca[0]); accb[0] = ffma2(pb, V0.x, accb[0]);
        acca[1] = ffma2(pa, V0.y, acca[1]); accb[1] = ffma2(pb, V0.y, accb[1]);
        acca[2] = ffma2(pa, V1.x, acca[2]); accb[2] = ffma2(pb, V1.x, accb[2]);
        acca[3] = ffma2(pa, V1.y, acca[3]); accb[3] = ffma2(pb, V1.y, accb[3]);
        acca[4] = ffma2(pa, V2.x, acca[4]); accb[4] = ffma2(pb, V2.x, accb[4]);
        acca[5] = ffma2(pa, V2.y, acca[5]); accb[5] = ffma2(pb, V2.y, accb[5]);
    }
    // diagonal key-pair (tokens 2uu, 2uu+1): query 2uu masks key 2uu+1
    {
        const ulonglong2* p = kvb + uu * 6;
        ulonglong2 K0 = p[0], K1 = p[1], K2 = p[2];
        ulonglong2 V0 = p[3], V1 = p[4], V2 = p[5];
        u64 sa = dot6(qa2, K0, K1, K2);
        u64 sb = dot6(qb2, K0, K1, K2);
        float saA, saB, sbA, sbB;
        unpack2(sa, saA, saB); unpack2(sb, sbA, sbB);
        (void)saB;
        u64 pa = pack2(ex2f(saA), 0.0f);
        u64 pb = pack2(ex2f(sbA), ex2f(sbB));
        la2 = fadd2(la2, pa); lb2 = fadd2(lb2, pb);
        acca[0] = ffma2(pa, V0.x, acca[0]); accb[0] = ffma2(pb, V0.x, accb[0]);
        acca[1] = ffma2(pa, V0.y, acca[1]); accb[1] = ffma2(pb, V0.y, accb[1]);
        acca[2] = ffma2(pa, V1.x, acca[2]); accb[2] = ffma2(pb, V1.x, accb[2]);
        acca[3] = ffma2(pa, V1.y, acca[3]); accb[3] = ffma2(pb, V1.y, accb[3]);
        acca[4] = ffma2(pa, V2.x, acca[4]); accb[4] = ffma2(pb, V2.x, accb[4]);
        acca[5] = ffma2(pa, V2.y, acca[5]); accb[5] = ffma2(pb, V2.y, accb[5]);
    }

    float lo, hi;
    unpack2(la2, lo, hi); float la = lo + hi;
    unpack2(lb2, lo, hi); float lb = lo + hi;
    float inva = rcpf(la), invb = rcpf(lb);
#pragma unroll
    for (int d = 0; d < DD; ++d) {
        unpack2(acca[d], lo, hi); oA[d] = (lo + hi) * inva;
        unpack2(accb[d], lo, hi); oB[d] = (lo + hi) * invb;
    }
}

// out-proj + residual + LN2 + FFN + residual for ONE token.
// Reloads x from global (L2 hit). __noinline__ confines register appetite.
__device__ __noinline__ void epilogue_tok(
    const float* __restrict__ o,
    const float* __restrict__ xt, float* __restrict__ ot,
    const float* __restrict__ s_w)
{
    const float* s_wo  = s_w + 126;
    const float* s_bo  = s_w + 162;
    const float* s_w1  = s_w + 168;
    const float* s_b1  = s_w + 204;
    const float* s_w2  = s_w + 210;
    const float* s_b2  = s_w + 246;
    const float* s_l2w = s_w + 264;
    const float* s_l2b = s_w + 270;

    float xv[DD];
    {
        float2 a = ((const float2*)xt)[0];
        float2 b = ((const float2*)xt)[1];
        float2 c = ((const float2*)xt)[2];
        xv[0] = a.x; xv[1] = a.y; xv[2] = b.x; xv[3] = b.y; xv[4] = c.x; xv[5] = c.y;
    }
    float y[DD];
#pragma unroll
    for (int d = 0; d < DD; ++d) {
        float a = s_bo[d];
#pragma unroll
        for (int i = 0; i < DD; ++i) a = fmaf(o[i], s_wo[i * 6 + d], a);
        y[d] = xv[d] + a;
    }
    float m = 0.f;
#pragma unroll
    for (int d = 0; d < DD; ++d) m += y[d];
    m *= (1.f / DD);
    float v = 0.f;
#pragma unroll
    for (int d = 0; d < DD; ++d) { float t = y[d] - m; v = fmaf(t, t, v); }
    float r = rsqrtf(v * (1.f / DD) + 1e-5f);
    float h2[DD];
#pragma unroll
    for (int d = 0; d < DD; ++d)
        h2[d] = fmaf((y[d] - m) * r, s_l2w[d], s_l2b[d]);
    float g[DD];
#pragma unroll
    for (int d = 0; d < DD; ++d) {
        float a = s_b1[d];
#pragma unroll
        for (int i = 0; i < DD; ++i) a = fmaf(h2[i], s_w1[i * 6 + d], a);
        g[d] = a * normcdff(a);           // exact gelu
    }
#pragma unroll
    for (int d = 0; d < DD; ++d) {
        float a = s_b2[d];
#pragma unroll
        for (int i = 0; i < DD; ++i) a = fmaf(g[i], s_w2[i * 6 + d], a);
        y[d] += a;                         // reuse y as result
    }
    ((float2*)ot)[0] = make_float2(y[0], y[1]);
    ((float2*)ot)[1] = make_float2(y[2], y[3]);
    ((float2*)ot)[2] = make_float2(y[4], y[5]);
}

// LN1 + QKV for tokens 2uu, 2uu+1 of one batch: produces duplicated-lane q
// (optional) and writes the K/V row. h values are returned for deferred q.
__device__ __forceinline__ void prologue_pair(
    const float* __restrict__ xt,      // x, token 2uu
    float* __restrict__ kv_row,        // s_kv row uu
    const float* __restrict__ s_w,
    float* __restrict__ hA, float* __restrict__ hB)
{
    const float* s_l1w = s_w + 252;
    const float* s_l1b = s_w + 258;
    float xv[12];
    {
        const float4* xp = (const float4*)xt;
        float4 X0 = xp[0], X1 = xp[1], X2 = xp[2];
        xv[0] = X0.x; xv[1] = X0.y; xv[2]  = X0.z; xv[3]  = X0.w;
        xv[4] = X1.x; xv[5] = X1.y; xv[6]  = X1.z; xv[7]  = X1.w;
        xv[8] = X2.x; xv[9] = X2.y; xv[10] = X2.z; xv[11] = X2.w;
    }
    float mA = 0.f, mB = 0.f;
#pragma unroll
    for (int j = 0; j < DD; ++j) { mA += xv[j]; mB += xv[6 + j]; }
    mA *= (1.f / DD); mB *= (1.f / DD);
    float vA = 0.f, vB = 0.f;
#pragma unroll
    for (int j = 0; j < DD; ++j) {
        float dA = xv[j] - mA;     vA = fmaf(dA, dA, vA);
        float dB = xv[6 + j] - mB; vB = fmaf(dB, dB, vB);
    }
    float rA = rsqrtf(vA * (1.f / DD) + 1e-5f);
    float rB = rsqrtf(vB * (1.f / DD) + 1e-5f);
#pragma unroll
    for (int j = 0; j < DD; ++j) {
        hA[j] = fmaf((xv[j] - mA) * rA,     s_l1w[j], s_l1b[j]);
        hB[j] = fmaf((xv[6 + j] - mB) * rB, s_l1w[j], s_l1b[j]);
    }
    // K,V (columns 6..17 of wqkv), pair-interleaved into the row
    const float* s_wqkv = s_w;
    const float* s_bqkv = s_w + 108;
    float kvA[12], kvB[12];
#pragma unroll
    for (int j = 0; j < 12; ++j) {
        float a = s_bqkv[6 + j], bq = s_bqkv[6 + j];
#pragma unroll
        for (int i = 0; i < DD; ++i) {
            a  = fmaf(hA[i], s_wqkv[i * 18 + 6 + j], a);
            bq = fmaf(hB[i], s_wqkv[i * 18 + 6 + j], bq);
        }
        kvA[j] = a; kvB[j] = bq;
    }
    float4* pp = (float4*)kv_row;
#pragma unroll
    for (int i = 0; i < 6; ++i)
        pp[i] = make_float4(kvA[2 * i], kvB[2 * i], kvA[2 * i + 1], kvB[2 * i + 1]);
}

__device__ __forceinline__ void make_q(
    const float* __restrict__ hA, const float* __restrict__ hB,
    const float* __restrict__ s_w, u64* __restrict__ qa2, u64* __restrict__ qb2)
{
    const float* s_wqkv = s_w;
    const float* s_bqkv = s_w + 108;
    const float SCL = 0.58897937652f;   // (1/sqrt6)*log2(e)
#pragma unroll
    for (int j = 0; j < DD; ++j) {
        float a = s_bqkv[j], bq = s_bqkv[j];
#pragma unroll
        for (int i = 0; i < DD; ++i) {
            a  = fmaf(hA[i], s_wqkv[i * 18 + j], a);
            bq = fmaf(hB[i], s_wqkv[i * 18 + j], bq);
        }
        a *= SCL; bq *= SCL;
        qa2[j] = pack2(a, a);
        qb2[j] = pack2(bq, bq);
    }
}

__global__ __launch_bounds__(128, 4) void block_ffn_kernel(
    const float* __restrict__ x,
    const float* __restrict__ ln1_w, const float* __restrict__ ln1_b,
    const float* __restrict__ wqkv,  const float* __restrict__ bqkv,
    const float* __restrict__ wo,    const float* __restrict__ bo,
    const float* __restrict__ ln2_w, const float* __restrict__ ln2_b,
    const float* __restrict__ w1,    const float* __restrict__ b1,
    const float* __restrict__ w2,    const float* __restrict__ b2,
    float* __restrict__ out)
{
    __shared__ float s_kv[4 * KV_STRIDE];   // 4 batches, pair-interleaved K/V
    __shared__ float s_w[276];

    const int t = threadIdx.x;
    const int b = t & 3;              // batch slot (interleaved in warp)
    const int u = t >> 2;             // first query-pair index, 0..31
    const int v = 63 - u;             // second query-pair (triangle fold)
    const int batch = blockIdx.x * 4 + b;

    // ---- stage weights (flat float layout, offsets as in epilogue_tok) ----
    if (t < 108) s_w[t] = wqkv[t];
    if (t < 18)  s_w[108 + t] = bqkv[t];
    if (t < 36) {
        s_w[126 + t] = wo[t];
        s_w[168 + t] = w1[t];
        s_w[210 + t] = w2[t];
    }
    if (t < DD) {
        s_w[162 + t] = bo[t];
        s_w[204 + t] = b1[t];
        s_w[246 + t] = b2[t];
        s_w[252 + t] = ln1_w[t];
        s_w[258 + t] = ln1_b[t];
        s_w[264 + t] = ln2_w[t];
        s_w[270 + t] = ln2_b[t];
    }
    __syncthreads();   // weights visible

    const float* xb = x   + (long)batch * SEQ * DD;
    float*       ob = out + (long)batch * SEQ * DD;
    float* kvbase = s_kv + b * KV_STRIDE;

    // ---- prologues for both query-pairs; K/V rows u and v ----
    float h1A[DD], h1B[DD], h2A[DD], h2B[DD];
    prologue_pair(xb + 2 * u * DD, kvbase + u * 24, s_w, h1A, h1B);
    prologue_pair(xb + 2 * v * DD, kvbase + v * 24, s_w, h2A, h2B);

    u64 qa2[DD], qb2[DD];
    make_q(h1A, h1B, s_w, qa2, qb2);

    __syncthreads();   // all K/V visible

    // ---- pair u: attention + epilogues ----
    {
        float oA[DD], oB[DD];
        attend(u, qa2, qb2, kvbase, oA, oB);
        epilogue_tok(oA, xb + (2 * u) * DD,     ob + (2 * u) * DD,     s_w);
        epilogue_tok(oB, xb + (2 * u + 1) * DD, ob + (2 * u + 1) * DD, s_w);
    }

    // ---- pair v = 63-u: attention + epilogues (q built from kept h) ----
    make_q(h2A, h2B, s_w, qa2, qb2);
    {
        float oA[DD], oB[DD];
        attend(v, qa2, qb2, kvbase, oA, oB);
        epilogue_tok(oA, xb + (2 * v) * DD,     ob + (2 * v) * DD,     s_w);
        epilogue_tok(oB, xb + (2 * v + 1) * DD, ob + (2 * v + 1) * DD, s_w);
    }
}

extern "C" void kernel_launch(void* const* d_in, const int* in_sizes, int n_in,
                              void* d_out, int out_size) {
    const float* x     = (const float*)d_in[0];
    const float* ln1_w = (const float*)d_in[1];
    const float* ln1_b = (const float*)d_in[2];
    const float* wqkv  = (const float*)d_in[3];
    const float* bqkv  = (const float*)d_in[4];
    const float* wo    = (const float*)d_in[5];
    const float* bo    = (const float*)d_in[6];
    const float* ln2_w = (const float*)d_in[7];
    const float* ln2_b = (const float*)d_in[8];
    const float* w1    = (const float*)d_in[9];
    const float* b1    = (const float*)d_in[10];
    const float* w2    = (const float*)d_in[11];
    const float* b2    = (const float*)d_in[12];
    float* out = (float*)d_out;

    const int B = in_sizes[0] / (SEQ * DD);   // 8192
    block_ffn_kernel<<<B / 4, 128>>>(x, ln1_w, ln1_b, wqkv, bqkv, wo, bo,
                                     ln2_w, ln2_b, w1, b1, w2, b2, out);
}